// round 2
// baseline (speedup 1.0000x reference)
#include <cuda_runtime.h>

#define T_STEPS 100
#define BB      512
#define NIN     784
#define HH      1024
#define OO      10

#define BETA    0.95f
#define DECAYC  0.05f   // DT / STDP_DECAY
#define A_PLUS  0.01f
#define A_MINUS 0.01f

#define NT      512               // threads per CTA
#define L0T     (NIN / 2)         // 392 threads own layer-0 (2 neurons each)
#define L0W     13                // warps touching layer 0 (392/32 = 12.25)
#define NZW     (2 * L0W)         // zero-mask words (j=0 block then j=1 block)

// Precomputed column-sums of W1 rows: colsum[h] = sum_k W1[h,k]
__device__ __align__(16) float g_colsum[HH];

// ---------------------------------------------------------------------------
// colsum kernel: one warp per row h. Deterministic (fixed stride + shfl tree).
// ---------------------------------------------------------------------------
__global__ void colsum_kernel(const float* __restrict__ W1) {
    int warp_in_block = threadIdx.x >> 5;
    int lane = threadIdx.x & 31;
    int h = blockIdx.x * (blockDim.x >> 5) + warp_in_block;
    if (h >= HH) return;
    float s = 0.f;
    for (int k = lane; k < NIN; k += 32) s += W1[(size_t)h * NIN + k];
#pragma unroll
    for (int off = 16; off; off >>= 1) s += __shfl_xor_sync(0xffffffffu, s, off);
    if (lane == 0) g_colsum[h] = s;
}

// ---------------------------------------------------------------------------
// Main SNN kernel: one block per batch element, whole T loop inside.
// 512 threads, thread t owns 2 consecutive neurons (float2 everywhere).
// All carry state in shared / registers -> only traffic is x reads + outputs.
// ---------------------------------------------------------------------------
__global__ void __launch_bounds__(NT)
snn_kernel(const float* __restrict__ x,
           const float* __restrict__ W1,
           const float* __restrict__ W2,
           const float* __restrict__ thr1,
           const float* __restrict__ thr2,
           float* __restrict__ out)
{
    __shared__ float2 s_mem0[L0T], s_pre0[L0T], s_post0[L0T];
    __shared__ float2 s_mem1[NT],  s_pre1[NT],  s_post1[NT];
    __shared__ unsigned s_zmask[32];        // [j*13 + w]
    __shared__ unsigned short s_zlist[NIN];
    __shared__ int s_nz;
    __shared__ float s_red[16][OO];

    const int b    = blockIdx.x;
    const int tid  = threadIdx.x;
    const int warp = tid >> 5;
    const int lane = tid & 31;
    const bool act0 = (tid < L0T);

    const float2 zero2 = make_float2(0.f, 0.f);

    if (act0) { s_mem0[tid] = zero2; s_pre0[tid] = zero2; s_post0[tid] = zero2; }
    s_mem1[tid] = zero2; s_pre1[tid] = zero2; s_post1[tid] = zero2;

    // per-thread constants for layer 1 (h = 2*tid + j)
    const float2 cs2  = ((const float2*)g_colsum)[tid];
    const float2 th12 = ((const float2*)thr1)[tid];

    // layer-2 state lives in registers of threads 0..9
    float mem2 = 0.f, pre2 = 0.f, post2 = 0.f, th2 = 0.f;
    if (tid < OO) th2 = thr2[tid];

    __syncthreads();

    // ---- output tensor bases (pytree order) ----
    const size_t S0 = (size_t)T_STEPS * BB * NIN;
    const size_t S1 = (size_t)T_STEPS * BB * HH;
    const size_t S2 = (size_t)T_STEPS * BB * OO;
    float* o_spk0  = out;
    float* o_pre0  = out + S0;
    float* o_post0 = out + 2 * S0;
    float* o_spk1  = out + 3 * S0;
    float* o_pre1  = out + 3 * S0 + S1;
    float* o_post1 = out + 3 * S0 + 2 * S1;
    float* o_spk2  = out + 3 * S0 + 3 * S1;
    float* o_mem2  = o_spk2 + S2;
    float* o_pre2  = o_spk2 + 2 * S2;
    float* o_post2 = o_spk2 + 3 * S2;

    const float2* W22 = (const float2*)W2;   // W2[o*HH + 2*tid+j] = W22[o*512 + tid]

    for (int t = 0; t < T_STEPS; ++t) {
        // ================= Layer 0 (thr = 0, subtract-reset => no-op) ===========
        const size_t base0 = ((size_t)t * BB + b) * NIN;
        float s0[2] = {0.f, 0.f};
        if (act0) {
            const float2 xt = __ldcs(&((const float2*)(x + base0))[tid]);
            float2 m = s_mem0[tid], pr = s_pre0[tid], po = s_post0[tid];
            float xin[2] = {xt.x, xt.y};
            float mm[2] = {m.x, m.y};
            float pp[2] = {pr.x, pr.y};
            float qq[2] = {po.x, po.y};
#pragma unroll
            for (int j = 0; j < 2; ++j) {
                float mn = BETA * mm[j] + xin[j];
                mm[j] = mn;
                float spk = (mn > 0.f) ? 1.f : 0.f;
                s0[j] = spk;
                pp[j] = pp[j] - DECAYC * pp[j] + A_PLUS * spk;
                qq[j] = qq[j] - DECAYC * qq[j] - A_MINUS * spk;
            }
            s_mem0[tid] = make_float2(mm[0], mm[1]);
            float2 prn = make_float2(pp[0], pp[1]);
            float2 pon = make_float2(qq[0], qq[1]);
            s_pre0[tid]  = prn;
            s_post0[tid] = pon;
            __stcs(&((float2*)(o_spk0  + base0))[tid], make_float2(s0[0], s0[1]));
            __stcs(&((float2*)(o_pre0  + base0))[tid], prn);
            __stcs(&((float2*)(o_post0 + base0))[tid], pon);
        }
        // zero-spike bitmask (fixed deterministic order)
        if (warp < L0W) {
#pragma unroll
            for (int j = 0; j < 2; ++j) {
                unsigned m = __ballot_sync(0xffffffffu, act0 && (s0[j] == 0.f));
                if (lane == 0) s_zmask[j * L0W + warp] = m;
            }
        }
        __syncthreads();

        // ========== expand bitmask -> ordered index list (warp 0 only) ==========
        if (warp == 0) {
            unsigned w = (lane < NZW) ? s_zmask[lane] : 0u;
            int cnt = __popc(w);
            int incl = cnt;
#pragma unroll
            for (int off = 1; off < 32; off <<= 1) {
                int v = __shfl_up_sync(0xffffffffu, incl, off);
                if (lane >= off) incl += v;
            }
            int pos = incl - cnt;
            int j  = (lane < L0W) ? 0 : 1;
            int wp = (lane < L0W) ? lane : lane - L0W;
            while (w) {
                int bit = __ffs(w) - 1;
                w &= w - 1;
                s_zlist[pos++] = (unsigned short)(64 * wp + 2 * bit + j);
            }
            if (lane == 31) s_nz = incl;
        }
        __syncthreads();
        const int nz = s_nz;

        // ================= Layer 1 (thr1, zero-reset) ===========================
        const size_t base1 = ((size_t)t * BB + b) * HH;
        float cur[2] = {cs2.x, cs2.y};
        for (int zj = 0; zj < nz; ++zj) {
            int kz = s_zlist[zj];
#pragma unroll
            for (int j = 0; j < 2; ++j)
                cur[j] -= W1[(size_t)(2 * tid + j) * NIN + kz];
        }
        float spk1[2];
        {
            float2 m = s_mem1[tid], pr = s_pre1[tid], po = s_post1[tid];
            float mm[2] = {m.x, m.y};
            float pp[2] = {pr.x, pr.y};
            float qq[2] = {po.x, po.y};
            float th[2] = {th12.x, th12.y};
#pragma unroll
            for (int j = 0; j < 2; ++j) {
                float c = fmaxf(cur[j], 0.f);
                float reset = (mm[j] > th[j]) ? 1.f : 0.f;
                float mn = (BETA * mm[j] + c) * (1.f - reset);
                mm[j] = mn;
                float spk = ((mn - th[j]) > 0.f) ? 1.f : 0.f;
                spk1[j] = spk;
                pp[j] = pp[j] - DECAYC * pp[j] + A_PLUS * spk;
                qq[j] = qq[j] - DECAYC * qq[j] - A_MINUS * spk;
            }
            s_mem1[tid] = make_float2(mm[0], mm[1]);
            float2 prn = make_float2(pp[0], pp[1]);
            float2 pon = make_float2(qq[0], qq[1]);
            s_pre1[tid]  = prn;
            s_post1[tid] = pon;
            __stcs(&((float2*)(o_spk1  + base1))[tid], make_float2(spk1[0], spk1[1]));
            __stcs(&((float2*)(o_pre1  + base1))[tid], prn);
            __stcs(&((float2*)(o_post1 + base1))[tid], pon);
        }

        // ================= Layer 2 dot: cur2[o] = sum_h spk1[h] * W2[o,h] =======
        float acc[OO];
#pragma unroll
        for (int o = 0; o < OO; ++o) {
            float2 w = W22[o * (HH / 2) + tid];
            acc[o] = spk1[0] * w.x + spk1[1] * w.y;
        }
#pragma unroll
        for (int o = 0; o < OO; ++o) {
#pragma unroll
            for (int off = 16; off; off >>= 1)
                acc[o] += __shfl_xor_sync(0xffffffffu, acc[o], off);
        }
        if (lane == 0) {
#pragma unroll
            for (int o = 0; o < OO; ++o) s_red[warp][o] = acc[o];
        }
        __syncthreads();

        if (tid < OO) {
            float c2 = 0.f;
#pragma unroll
            for (int w = 0; w < 16; ++w) c2 += s_red[w][tid];
            c2 = fmaxf(c2, 0.f);
            float reset = (mem2 > th2) ? 1.f : 0.f;
            mem2 = (BETA * mem2 + c2) * (1.f - reset);
            float spk = ((mem2 - th2) > 0.f) ? 1.f : 0.f;
            pre2  = pre2  - DECAYC * pre2  + A_PLUS  * spk;
            post2 = post2 - DECAYC * post2 - A_MINUS * spk;
            const size_t base2 = ((size_t)t * BB + b) * OO + tid;
            __stcs(o_spk2  + base2, spk);
            __stcs(o_mem2  + base2, mem2);
            __stcs(o_pre2  + base2, pre2);
            __stcs(o_post2 + base2, post2);
        }
        __syncthreads();   // protect s_red / s_zmask / s_zlist for next iteration
    }
}

// ---------------------------------------------------------------------------
extern "C" void kernel_launch(void* const* d_in, const int* in_sizes, int n_in,
                              void* d_out, int out_size) {
    const float* x    = (const float*)d_in[0];
    const float* W1   = (const float*)d_in[1];
    const float* W2   = (const float*)d_in[2];
    const float* thr1 = (const float*)d_in[3];
    const float* thr2 = (const float*)d_in[4];
    float* out = (float*)d_out;
    (void)in_sizes; (void)n_in; (void)out_size;

    colsum_kernel<<<HH / 4, 128>>>(W1);
    snn_kernel<<<BB, NT>>>(x, W1, W2, thr1, thr2, out);
}

// round 3
// speedup vs baseline: 1.3006x; 1.3006x over previous
#include <cuda_runtime.h>

#define T_STEPS 100
#define BB      512
#define NIN     784
#define HH      1024
#define OO      10

#define BETA    0.95f
#define DECAYC  0.05f   // DT / STDP_DECAY
#define A_PLUS  0.01f
#define A_MINUS 0.01f

#define NT      256
#define L0T     (NIN / 4)   // 196 threads own layer 0 (4 neurons each)

// Precomputed column-sums of W1 rows: colsum[h] = sum_k W1[h,k]
__device__ __align__(16) float g_colsum[HH];

// ---------------------------------------------------------------------------
// colsum kernel: one warp per row h. Deterministic (fixed stride + shfl tree).
// ---------------------------------------------------------------------------
__global__ void colsum_kernel(const float* __restrict__ W1) {
    int warp_in_block = threadIdx.x >> 5;
    int lane = threadIdx.x & 31;
    int h = blockIdx.x * (blockDim.x >> 5) + warp_in_block;
    if (h >= HH) return;
    float s = 0.f;
    for (int k = lane; k < NIN; k += 32) s += W1[(size_t)h * NIN + k];
#pragma unroll
    for (int off = 16; off; off >>= 1) s += __shfl_xor_sync(0xffffffffu, s, off);
    if (lane == 0) g_colsum[h] = s;
}

// ---------------------------------------------------------------------------
// Main SNN kernel: one block per batch element, whole T loop inside.
// 256 threads, thread t owns 4 consecutive neurons. ALL carry state lives in
// registers; shared memory only for the (rare) zero-spike list and the tiny
// layer-2 reduction. Global traffic = x reads + output writes only.
// ---------------------------------------------------------------------------
__global__ void __launch_bounds__(NT)
snn_kernel(const float* __restrict__ x,
           const float* __restrict__ W1,
           const float* __restrict__ W2,
           const float* __restrict__ thr1,
           const float* __restrict__ thr2,
           float* __restrict__ out)
{
    __shared__ unsigned s_zmask[32];
    __shared__ unsigned short s_zlist[NIN];
    __shared__ int s_nz;
    __shared__ float s_red[8][OO];

    const int b    = blockIdx.x;
    const int tid  = threadIdx.x;
    const int warp = tid >> 5;
    const int lane = tid & 31;
    const bool act0 = (tid < L0T);

    // ---- register-resident carries ----
    float mem0[4] = {0,0,0,0}, pre0[4] = {0,0,0,0}, post0[4] = {0,0,0,0};
    float mem1[4] = {0,0,0,0}, pre1[4] = {0,0,0,0}, post1[4] = {0,0,0,0};

    const float4 cs4  = ((const float4*)g_colsum)[tid];
    const float4 th14 = ((const float4*)thr1)[tid];
    const float th1r[4] = {th14.x, th14.y, th14.z, th14.w};

    float mem2 = 0.f, pre2 = 0.f, post2 = 0.f, th2 = 0.f;
    if (tid < OO) th2 = thr2[tid];

    // ---- output tensor bases (pytree order) ----
    const size_t S0 = (size_t)T_STEPS * BB * NIN;
    const size_t S1 = (size_t)T_STEPS * BB * HH;
    const size_t S2 = (size_t)T_STEPS * BB * OO;
    float* o_spk0  = out;
    float* o_pre0  = out + S0;
    float* o_post0 = out + 2 * S0;
    float* o_spk1  = out + 3 * S0;
    float* o_pre1  = out + 3 * S0 + S1;
    float* o_post1 = out + 3 * S0 + 2 * S1;
    float* o_spk2  = out + 3 * S0 + 3 * S1;
    float* o_mem2  = o_spk2 + S2;
    float* o_pre2  = o_spk2 + 2 * S2;
    float* o_post2 = o_spk2 + 3 * S2;

    const float4* W24 = (const float4*)W2;   // W2[o*HH + 4*tid+j] = W24[o*256 + tid]

    for (int t = 0; t < T_STEPS; ++t) {
        // ================= Layer 0 (thr = 0, subtract-reset => no-op) ===========
        const size_t base0 = ((size_t)t * BB + b) * NIN;
        float s0[4] = {0.f, 0.f, 0.f, 0.f};
        if (act0) {
            const float4 xt = __ldcs(&((const float4*)(x + base0))[tid]);
            const float xin[4] = {xt.x, xt.y, xt.z, xt.w};
#pragma unroll
            for (int j = 0; j < 4; ++j) {
                float mn = BETA * mem0[j] + xin[j];
                mem0[j] = mn;
                float spk = (mn > 0.f) ? 1.f : 0.f;
                s0[j] = spk;
                pre0[j]  = pre0[j]  - DECAYC * pre0[j]  + A_PLUS  * spk;
                post0[j] = post0[j] - DECAYC * post0[j] - A_MINUS * spk;
            }
            __stcs(&((float4*)(o_spk0  + base0))[tid], make_float4(s0[0], s0[1], s0[2], s0[3]));
            __stcs(&((float4*)(o_pre0  + base0))[tid], make_float4(pre0[0], pre0[1], pre0[2], pre0[3]));
            __stcs(&((float4*)(o_post0 + base0))[tid], make_float4(post0[0], post0[1], post0[2], post0[3]));
        }

        // ---- fast zero-spike check (expected: none) ----
        const bool has_zero = act0 &&
            (s0[0] == 0.f || s0[1] == 0.f || s0[2] == 0.f || s0[3] == 0.f);
        const int anyz = __syncthreads_count(has_zero);

        int nz = 0;
        if (anyz != 0) {
            // slow path: build ordered zero list (deterministic order)
#pragma unroll
            for (int j = 0; j < 4; ++j) {
                unsigned m = __ballot_sync(0xffffffffu, act0 && (s0[j] == 0.f));
                if (lane == 0) s_zmask[j * 8 + warp] = m;
            }
            __syncthreads();
            if (warp == 0) {
                unsigned w = s_zmask[lane];
                int cnt = __popc(w);
                int incl = cnt;
#pragma unroll
                for (int off = 1; off < 32; off <<= 1) {
                    int v = __shfl_up_sync(0xffffffffu, incl, off);
                    if (lane >= off) incl += v;
                }
                int pos = incl - cnt;
                int j = lane >> 3, wp = lane & 7;
                while (w) {
                    int bit = __ffs(w) - 1;
                    w &= w - 1;
                    s_zlist[pos++] = (unsigned short)(4 * (wp * 32 + bit) + j);
                }
                if (lane == 31) s_nz = incl;
            }
            __syncthreads();
            nz = s_nz;
        }

        // ================= Layer 1 (thr1, zero-reset) ===========================
        const size_t base1 = ((size_t)t * BB + b) * HH;
        float cur[4] = {cs4.x, cs4.y, cs4.z, cs4.w};
        for (int zj = 0; zj < nz; ++zj) {
            int kz = s_zlist[zj];
#pragma unroll
            for (int j = 0; j < 4; ++j)
                cur[j] -= W1[(size_t)(4 * tid + j) * NIN + kz];
        }
        float spk1[4];
#pragma unroll
        for (int j = 0; j < 4; ++j) {
            float c = fmaxf(cur[j], 0.f);
            float reset = (mem1[j] > th1r[j]) ? 1.f : 0.f;
            float mn = (BETA * mem1[j] + c) * (1.f - reset);
            mem1[j] = mn;
            float spk = ((mn - th1r[j]) > 0.f) ? 1.f : 0.f;
            spk1[j] = spk;
            pre1[j]  = pre1[j]  - DECAYC * pre1[j]  + A_PLUS  * spk;
            post1[j] = post1[j] - DECAYC * post1[j] - A_MINUS * spk;
        }
        __stcs(&((float4*)(o_spk1  + base1))[tid], make_float4(spk1[0], spk1[1], spk1[2], spk1[3]));
        __stcs(&((float4*)(o_pre1  + base1))[tid], make_float4(pre1[0], pre1[1], pre1[2], pre1[3]));
        __stcs(&((float4*)(o_post1 + base1))[tid], make_float4(post1[0], post1[1], post1[2], post1[3]));

        // ================= Layer 2 dot: cur2[o] = sum_h spk1[h] * W2[o,h] =======
        float acc[OO];
#pragma unroll
        for (int o = 0; o < OO; ++o) {
            float4 w = __ldg(&W24[o * (HH / 4) + tid]);
            acc[o] = spk1[0] * w.x + spk1[1] * w.y + spk1[2] * w.z + spk1[3] * w.w;
        }
#pragma unroll
        for (int o = 0; o < OO; ++o) {
#pragma unroll
            for (int off = 16; off; off >>= 1)
                acc[o] += __shfl_xor_sync(0xffffffffu, acc[o], off);
        }
        if (lane == 0) {
#pragma unroll
            for (int o = 0; o < OO; ++o) s_red[warp][o] = acc[o];
        }
        __syncthreads();

        if (tid < OO) {
            float c2 = 0.f;
#pragma unroll
            for (int w = 0; w < 8; ++w) c2 += s_red[w][tid];
            c2 = fmaxf(c2, 0.f);
            float reset = (mem2 > th2) ? 1.f : 0.f;
            mem2 = (BETA * mem2 + c2) * (1.f - reset);
            float spk = ((mem2 - th2) > 0.f) ? 1.f : 0.f;
            pre2  = pre2  - DECAYC * pre2  + A_PLUS  * spk;
            post2 = post2 - DECAYC * post2 - A_MINUS * spk;
            const size_t base2 = ((size_t)t * BB + b) * OO + tid;
            __stcs(o_spk2  + base2, spk);
            __stcs(o_mem2  + base2, mem2);
            __stcs(o_pre2  + base2, pre2);
            __stcs(o_post2 + base2, post2);
        }
        __syncthreads();   // protect s_red (and zero-list smem) for next iteration
    }
}

// ---------------------------------------------------------------------------
extern "C" void kernel_launch(void* const* d_in, const int* in_sizes, int n_in,
                              void* d_out, int out_size) {
    const float* x    = (const float*)d_in[0];
    const float* W1   = (const float*)d_in[1];
    const float* W2   = (const float*)d_in[2];
    const float* thr1 = (const float*)d_in[3];
    const float* thr2 = (const float*)d_in[4];
    float* out = (float*)d_out;
    (void)in_sizes; (void)n_in; (void)out_size;

    colsum_kernel<<<HH / 4, 128>>>(W1);
    snn_kernel<<<BB, NT>>>(x, W1, W2, thr1, thr2, out);
}

// round 4
// speedup vs baseline: 1.5000x; 1.1533x over previous
#include <cuda_runtime.h>

#define T_STEPS 100
#define BB      512
#define NIN     784
#define HH      1024
#define OO      10

#define BETA    0.95f
#define DECAYC  0.05f   // DT / STDP_DECAY
#define A_PLUS  0.01f
#define A_MINUS 0.01f

#define NIN4    (NIN / 4)     // 196
#define TBB     (T_STEPS * BB)

// ---------------- scratch (static device memory, no allocs) ----------------
__device__ __align__(16) float g_colsum[HH];
__device__ int            g_zcnt[TBB];              // zero-spike count per (t,b)
__device__ unsigned short g_zidx[(size_t)TBB * NIN]; // zero-spike indices
__device__ float          g_cur2[(size_t)TBB * OO];  // relu(spk1 @ W2^T)

// ---------------------------------------------------------------------------
// Zero the per-(t,b) zero-spike counters (needed every replay).
// ---------------------------------------------------------------------------
__global__ void zero_kernel() {
    int i = blockIdx.x * blockDim.x + threadIdx.x;
    if (i < TBB) g_zcnt[i] = 0;
}

// ---------------------------------------------------------------------------
// colsum kernel: one warp per row h (deterministic shfl tree).
// ---------------------------------------------------------------------------
__global__ void colsum_kernel(const float* __restrict__ W1) {
    int warp_in_block = threadIdx.x >> 5;
    int lane = threadIdx.x & 31;
    int h = blockIdx.x * (blockDim.x >> 5) + warp_in_block;
    if (h >= HH) return;
    float s = 0.f;
    for (int k = lane; k < NIN; k += 32) s += W1[(size_t)h * NIN + k];
#pragma unroll
    for (int off = 16; off; off >>= 1) s += __shfl_xor_sync(0xffffffffu, s, off);
    if (lane == 0) g_colsum[h] = s;
}

// ---------------------------------------------------------------------------
// Kernel A: layer 0. Fully parallel, barrier-free streaming scan.
// Thread owns (b, 4 input neurons); loops t with x prefetch.
// Writes spk0/pre0/post0 (84% of all output bytes) + rare zero-spike records.
// ---------------------------------------------------------------------------
__global__ void __launch_bounds__(256)
layer0_kernel(const float* __restrict__ x, float* __restrict__ out)
{
    const int id = blockIdx.x * blockDim.x + threadIdx.x;   // 0 .. 512*196-1
    const int b  = id / NIN4;
    const int q  = id - b * NIN4;          // float4 index within row

    const size_t S0 = (size_t)T_STEPS * BB * NIN;
    float4* o_spk0  = (float4*)out;
    float4* o_pre0  = (float4*)(out + S0);
    float4* o_post0 = (float4*)(out + 2 * S0);
    const float4* x4 = (const float4*)x;

    const size_t stride = (size_t)BB * NIN4;       // per-t stride in float4
    size_t p = (size_t)b * NIN4 + q;

    float mem0[4] = {0,0,0,0}, pre0[4] = {0,0,0,0}, post0[4] = {0,0,0,0};

    float4 xt = __ldcs(&x4[p]);
    for (int t = 0; t < T_STEPS; ++t) {
        float4 xn;
        if (t + 1 < T_STEPS) xn = __ldcs(&x4[p + (size_t)(t + 1) * stride]);
        const float xin[4] = {xt.x, xt.y, xt.z, xt.w};
        float s0[4];
#pragma unroll
        for (int j = 0; j < 4; ++j) {
            float mn = BETA * mem0[j] + xin[j];    // thr = 0, subtract-reset no-op
            mem0[j] = mn;
            float spk = (mn > 0.f) ? 1.f : 0.f;
            s0[j] = spk;
            pre0[j]  = pre0[j]  - DECAYC * pre0[j]  + A_PLUS  * spk;
            post0[j] = post0[j] - DECAYC * post0[j] - A_MINUS * spk;
        }
        const size_t op = p + (size_t)t * stride;
        __stcs(&o_spk0[op],  make_float4(s0[0], s0[1], s0[2], s0[3]));
        __stcs(&o_pre0[op],  make_float4(pre0[0], pre0[1], pre0[2], pre0[3]));
        __stcs(&o_post0[op], make_float4(post0[0], post0[1], post0[2], post0[3]));
        // rare: record zero spikes for layer-1 correction
        if (s0[0] == 0.f || s0[1] == 0.f || s0[2] == 0.f || s0[3] == 0.f) {
            const int tb = t * BB + b;
#pragma unroll
            for (int j = 0; j < 4; ++j) {
                if (s0[j] == 0.f) {
                    int pos = atomicAdd(&g_zcnt[tb], 1);
                    g_zidx[(size_t)tb * NIN + pos] = (unsigned short)(4 * q + j);
                }
            }
        }
        xt = xn;
    }
}

// ---------------------------------------------------------------------------
// Kernel B: layer 1 + cur2 partial GEMM. CTA per b, 256 threads own 4 h each.
// W2 slice + all carries in registers; ONE barrier per step (dbl-buffered).
// ---------------------------------------------------------------------------
__global__ void __launch_bounds__(256)
layer1_kernel(const float* __restrict__ W1,
              const float* __restrict__ W2,
              const float* __restrict__ thr1,
              float* __restrict__ out)
{
    __shared__ float s_red[2][8][OO];

    const int b    = blockIdx.x;
    const int tid  = threadIdx.x;
    const int warp = tid >> 5;
    const int lane = tid & 31;

    const size_t S0 = (size_t)T_STEPS * BB * NIN;
    const size_t S1 = (size_t)T_STEPS * BB * HH;
    float4* o_spk1  = (float4*)(out + 3 * S0);
    float4* o_pre1  = (float4*)(out + 3 * S0 + S1);
    float4* o_post1 = (float4*)(out + 3 * S0 + 2 * S1);

    const float4 cs4  = ((const float4*)g_colsum)[tid];
    const float4 th14 = ((const float4*)thr1)[tid];
    const float th1r[4] = {th14.x, th14.y, th14.z, th14.w};

    // loop-invariant W2 slice in registers: W2[o][4*tid .. 4*tid+3]
    float4 w2r[OO];
#pragma unroll
    for (int o = 0; o < OO; ++o) w2r[o] = ((const float4*)W2)[o * (HH / 4) + tid];

    float mem1[4] = {0,0,0,0}, pre1[4] = {0,0,0,0}, post1[4] = {0,0,0,0};

    for (int t = 0; t < T_STEPS; ++t) {
        const int tb = t * BB + b;
        float cur[4] = {cs4.x, cs4.y, cs4.z, cs4.w};
        const int nz = g_zcnt[tb];
        if (nz != 0) {
            for (int zj = 0; zj < nz; ++zj) {
                int kz = g_zidx[(size_t)tb * NIN + zj];
#pragma unroll
                for (int j = 0; j < 4; ++j)
                    cur[j] -= W1[(size_t)(4 * tid + j) * NIN + kz];
            }
        }
        float spk1[4];
#pragma unroll
        for (int j = 0; j < 4; ++j) {
            float c = fmaxf(cur[j], 0.f);
            float reset = (mem1[j] > th1r[j]) ? 1.f : 0.f;
            float mn = (BETA * mem1[j] + c) * (1.f - reset);
            mem1[j] = mn;
            float spk = ((mn - th1r[j]) > 0.f) ? 1.f : 0.f;
            spk1[j] = spk;
            pre1[j]  = pre1[j]  - DECAYC * pre1[j]  + A_PLUS  * spk;
            post1[j] = post1[j] - DECAYC * post1[j] - A_MINUS * spk;
        }
        const size_t op = (size_t)tb * (HH / 4) + tid;
        __stcs(&o_spk1[op],  make_float4(spk1[0], spk1[1], spk1[2], spk1[3]));
        __stcs(&o_pre1[op],  make_float4(pre1[0], pre1[1], pre1[2], pre1[3]));
        __stcs(&o_post1[op], make_float4(post1[0], post1[1], post1[2], post1[3]));

        // partial dots for cur2
        float acc[OO];
#pragma unroll
        for (int o = 0; o < OO; ++o)
            acc[o] = spk1[0] * w2r[o].x + spk1[1] * w2r[o].y +
                     spk1[2] * w2r[o].z + spk1[3] * w2r[o].w;
#pragma unroll
        for (int o = 0; o < OO; ++o) {
#pragma unroll
            for (int off = 16; off; off >>= 1)
                acc[o] += __shfl_xor_sync(0xffffffffu, acc[o], off);
        }
        const int buf = t & 1;
        if (lane == 0) {
#pragma unroll
            for (int o = 0; o < OO; ++o) s_red[buf][warp][o] = acc[o];
        }
        __syncthreads();
        if (tid < OO) {
            float c2 = 0.f;
#pragma unroll
            for (int w = 0; w < 8; ++w) c2 += s_red[buf][w][tid];
            g_cur2[(size_t)tb * OO + tid] = fmaxf(c2, 0.f);
        }
    }
}

// ---------------------------------------------------------------------------
// Kernel C: layer 2 scan. Thread per (b, o); reads L2-resident cur2.
// ---------------------------------------------------------------------------
__global__ void __launch_bounds__(256)
layer2_kernel(const float* __restrict__ thr2, float* __restrict__ out)
{
    const int id = blockIdx.x * blockDim.x + threadIdx.x;   // 0 .. 5119
    if (id >= BB * OO) return;
    const int o = id % OO;

    const size_t S0 = (size_t)T_STEPS * BB * NIN;
    const size_t S1 = (size_t)T_STEPS * BB * HH;
    const size_t S2 = (size_t)T_STEPS * BB * OO;
    float* o_spk2  = out + 3 * S0 + 3 * S1;
    float* o_mem2  = o_spk2 + S2;
    float* o_pre2  = o_spk2 + 2 * S2;
    float* o_post2 = o_spk2 + 3 * S2;

    const float th2 = thr2[o];
    float mem2 = 0.f, pre2 = 0.f, post2 = 0.f;

    float c2 = g_cur2[id];
    for (int t = 0; t < T_STEPS; ++t) {
        float cn = (t + 1 < T_STEPS) ? g_cur2[(size_t)(t + 1) * BB * OO + id] : 0.f;
        float reset = (mem2 > th2) ? 1.f : 0.f;
        mem2 = (BETA * mem2 + c2) * (1.f - reset);   // c2 already relu'd
        float spk = ((mem2 - th2) > 0.f) ? 1.f : 0.f;
        pre2  = pre2  - DECAYC * pre2  + A_PLUS  * spk;
        post2 = post2 - DECAYC * post2 - A_MINUS * spk;
        const size_t p = (size_t)t * BB * OO + id;
        __stcs(o_spk2  + p, spk);
        __stcs(o_mem2  + p, mem2);
        __stcs(o_pre2  + p, pre2);
        __stcs(o_post2 + p, post2);
        c2 = cn;
    }
}

// ---------------------------------------------------------------------------
extern "C" void kernel_launch(void* const* d_in, const int* in_sizes, int n_in,
                              void* d_out, int out_size) {
    const float* x    = (const float*)d_in[0];
    const float* W1   = (const float*)d_in[1];
    const float* W2   = (const float*)d_in[2];
    const float* thr1 = (const float*)d_in[3];
    const float* thr2 = (const float*)d_in[4];
    float* out = (float*)d_out;
    (void)in_sizes; (void)n_in; (void)out_size;

    zero_kernel<<<(TBB + 1023) / 1024, 1024>>>();
    colsum_kernel<<<HH / 4, 128>>>(W1);
    layer0_kernel<<<(BB * NIN4) / 256, 256>>>(x, out);
    layer1_kernel<<<BB, 256>>>(W1, W2, thr1, out);
    layer2_kernel<<<(BB * OO + 255) / 256, 256>>>(thr2, out);
}